// round 4
// baseline (speedup 1.0000x reference)
#include <cuda_runtime.h>

#define EMBED  1024
#define NHEAD  16
#define HDIM   64
#define BATCH  2
#define QLEN   2048
#define CLEN   2048
#define ROWS   (BATCH * QLEN)   // 4096

// ---------------- scratch (device globals: allocation-free) ----------------
__device__ float g_Q[(size_t)ROWS * EMBED];
__device__ float g_K[(size_t)ROWS * EMBED];
__device__ float g_V[(size_t)ROWS * EMBED];
__device__ float g_A[(size_t)ROWS * EMBED];

// ---------------- SGEMM 128x128x16, C = A@W + bias  (M=4096,N=1024,K=1024) --
__global__ void __launch_bounds__(256, 2)
sgemm_bias(const float* __restrict__ A, const float* __restrict__ W,
           const float* __restrict__ bias, float* __restrict__ C)
{
    const int M = 4096, N = 1024, K = 1024;
    (void)M;
    __shared__ float As[16][128];   // [k][m] (transposed)
    __shared__ float Ws[16][128];   // [k][n]

    const int tid = threadIdx.x;
    const int bm  = blockIdx.y * 128;
    const int bn  = blockIdx.x * 128;
    const int tr  = tid >> 4;       // 0..15 -> rows tr*8..tr*8+7
    const int tc  = tid & 15;       // 0..15 -> cols tc*8..tc*8+7

    // loader indices
    const int a_row = tid >> 2;           // 0..63 (+64 second half)
    const int a_k4  = (tid & 3) * 4;
    const int w_k   = tid >> 5;           // 0..7 (+8 second half)
    const int w_c   = (tid & 31) * 4;

    float acc[8][8];
    #pragma unroll
    for (int i = 0; i < 8; i++)
        #pragma unroll
        for (int j = 0; j < 8; j++) acc[i][j] = 0.f;

    for (int kt = 0; kt < K; kt += 16) {
        #pragma unroll
        for (int half = 0; half < 2; half++) {
            int row = a_row + half * 64;
            float4 v = *(const float4*)&A[(size_t)(bm + row) * K + kt + a_k4];
            As[a_k4 + 0][row] = v.x;
            As[a_k4 + 1][row] = v.y;
            As[a_k4 + 2][row] = v.z;
            As[a_k4 + 3][row] = v.w;
        }
        #pragma unroll
        for (int half = 0; half < 2; half++) {
            int k = w_k + half * 8;
            float4 v = *(const float4*)&W[(size_t)(kt + k) * N + bn + w_c];
            *(float4*)&Ws[k][w_c] = v;
        }
        __syncthreads();

        #pragma unroll
        for (int k = 0; k < 16; k++) {
            float4 a0 = *(const float4*)&As[k][tr * 8];
            float4 a1 = *(const float4*)&As[k][tr * 8 + 4];
            float4 b0 = *(const float4*)&Ws[k][tc * 8];
            float4 b1 = *(const float4*)&Ws[k][tc * 8 + 4];
            float a[8] = {a0.x, a0.y, a0.z, a0.w, a1.x, a1.y, a1.z, a1.w};
            float b[8] = {b0.x, b0.y, b0.z, b0.w, b1.x, b1.y, b1.z, b1.w};
            #pragma unroll
            for (int i = 0; i < 8; i++)
                #pragma unroll
                for (int j = 0; j < 8; j++)
                    acc[i][j] = fmaf(a[i], b[j], acc[i][j]);
        }
        __syncthreads();
    }

    // epilogue: + bias, float4 stores
    float bsv[8];
    #pragma unroll
    for (int j = 0; j < 8; j++) bsv[j] = __ldg(&bias[bn + tc * 8 + j]);
    #pragma unroll
    for (int i = 0; i < 8; i++) {
        size_t off = (size_t)(bm + tr * 8 + i) * N + bn + tc * 8;
        float4 r0 = make_float4(acc[i][0] + bsv[0], acc[i][1] + bsv[1],
                                acc[i][2] + bsv[2], acc[i][3] + bsv[3]);
        float4 r1 = make_float4(acc[i][4] + bsv[4], acc[i][5] + bsv[5],
                                acc[i][6] + bsv[6], acc[i][7] + bsv[7]);
        *(float4*)&C[off]     = r0;
        *(float4*)&C[off + 4] = r1;
    }
}

// ---------------- flash attention (fp32, online softmax) -------------------
// grid: (QLEN/128, BATCH*NHEAD), block 256.
// Q,K,V,O all [B*L, 1024] row-major, head slice at h*64.
#define BQ 128
#define BKV 128
#define QS_STRIDE 65
#define KS_STRIDE 65
#define VS_STRIDE 68
#define PS_STRIDE 132
#define FLASH_SMEM_FLOATS (BQ*QS_STRIDE + BKV*KS_STRIDE + BKV*VS_STRIDE + BQ*PS_STRIDE)

__global__ void __launch_bounds__(256, 1)
flash_attn(const float* __restrict__ Q, const float* __restrict__ K,
           const float* __restrict__ V, float* __restrict__ O)
{
    extern __shared__ float sm[];
    float* Qs = sm;
    float* Ks = Qs + BQ * QS_STRIDE;
    float* Vs = Ks + BKV * KS_STRIDE;
    float* Ps = Vs + BKV * VS_STRIDE;

    const int tid = threadIdx.x;
    const int bh  = blockIdx.y;
    const int b   = bh >> 4;
    const int h   = bh & 15;
    const int q0  = blockIdx.x * BQ;
    const int tr  = tid >> 4;    // 0..15 -> q rows tr*8..+7
    const int tc  = tid & 15;    // 0..15

    const float scale = 0.125f;  // 1/sqrt(64)

    const float* Qg = Q + ((size_t)(b * QLEN + q0)) * EMBED + h * HDIM;
    const float* Kg = K + ((size_t)b * CLEN) * EMBED + h * HDIM;
    const float* Vg = V + ((size_t)b * CLEN) * EMBED + h * HDIM;

    // load Q tile (pre-scaled)
    #pragma unroll
    for (int i = 0; i < 8; i++) {
        int f = tid + i * 256;          // 0..2047 float4s
        int row = f >> 4;
        int c4  = (f & 15) * 4;
        float4 v = *(const float4*)&Qg[(size_t)row * EMBED + c4];
        float* q = &Qs[row * QS_STRIDE + c4];
        q[0] = v.x * scale; q[1] = v.y * scale; q[2] = v.z * scale; q[3] = v.w * scale;
    }

    float m[8], l[8], o[8][4];
    #pragma unroll
    for (int i = 0; i < 8; i++) {
        m[i] = -1e30f; l[i] = 0.f;
        o[i][0] = o[i][1] = o[i][2] = o[i][3] = 0.f;
    }

    for (int kt = 0; kt < CLEN; kt += BKV) {
        // load K,V tile
        #pragma unroll
        for (int i = 0; i < 8; i++) {
            int f = tid + i * 256;
            int row = f >> 4;
            int c4  = (f & 15) * 4;
            float4 kv = *(const float4*)&Kg[(size_t)(kt + row) * EMBED + c4];
            float* kd = &Ks[row * KS_STRIDE + c4];
            kd[0] = kv.x; kd[1] = kv.y; kd[2] = kv.z; kd[3] = kv.w;
            float4 vv = *(const float4*)&Vg[(size_t)(kt + row) * EMBED + c4];
            *(float4*)&Vs[row * VS_STRIDE + c4] = vv;
        }
        __syncthreads();

        // S = Q K^T (scaled), 8x8 per thread
        float s[8][8];
        #pragma unroll
        for (int i = 0; i < 8; i++)
            #pragma unroll
            for (int j = 0; j < 8; j++) s[i][j] = 0.f;

        #pragma unroll 4
        for (int d = 0; d < HDIM; d++) {
            float a[8], bb[8];
            #pragma unroll
            for (int i = 0; i < 8; i++) a[i]  = Qs[(tr * 8 + i) * QS_STRIDE + d];
            #pragma unroll
            for (int j = 0; j < 8; j++) bb[j] = Ks[(tc * 8 + j) * KS_STRIDE + d];
            #pragma unroll
            for (int i = 0; i < 8; i++)
                #pragma unroll
                for (int j = 0; j < 8; j++)
                    s[i][j] = fmaf(a[i], bb[j], s[i][j]);
        }

        // online softmax per row (16-lane row-group reductions)
        #pragma unroll
        for (int i = 0; i < 8; i++) {
            float rm = s[i][0];
            #pragma unroll
            for (int j = 1; j < 8; j++) rm = fmaxf(rm, s[i][j]);
            rm = fmaxf(rm, __shfl_xor_sync(0xffffffffu, rm, 8));
            rm = fmaxf(rm, __shfl_xor_sync(0xffffffffu, rm, 4));
            rm = fmaxf(rm, __shfl_xor_sync(0xffffffffu, rm, 2));
            rm = fmaxf(rm, __shfl_xor_sync(0xffffffffu, rm, 1));
            float mn = fmaxf(m[i], rm);
            float alpha = __expf(m[i] - mn);
            m[i] = mn;
            float rs = 0.f;
            #pragma unroll
            for (int j = 0; j < 8; j++) {
                s[i][j] = __expf(s[i][j] - mn);
                rs += s[i][j];
            }
            rs += __shfl_xor_sync(0xffffffffu, rs, 8);
            rs += __shfl_xor_sync(0xffffffffu, rs, 4);
            rs += __shfl_xor_sync(0xffffffffu, rs, 2);
            rs += __shfl_xor_sync(0xffffffffu, rs, 1);
            l[i] = l[i] * alpha + rs;
            o[i][0] *= alpha; o[i][1] *= alpha; o[i][2] *= alpha; o[i][3] *= alpha;
        }

        // stage P to smem
        #pragma unroll
        for (int i = 0; i < 8; i++) {
            float* pr = &Ps[(tr * 8 + i) * PS_STRIDE + tc * 8];
            *(float4*)&pr[0] = make_float4(s[i][0], s[i][1], s[i][2], s[i][3]);
            *(float4*)&pr[4] = make_float4(s[i][4], s[i][5], s[i][6], s[i][7]);
        }
        __syncthreads();

        // O += P @ V  (8 rows x 4 cols per thread, cols = tc*4..tc*4+3)
        #pragma unroll 2
        for (int k = 0; k < BKV; k++) {
            float4 v4 = *(const float4*)&Vs[k * VS_STRIDE + tc * 4];
            #pragma unroll
            for (int i = 0; i < 8; i++) {
                float p = Ps[(tr * 8 + i) * PS_STRIDE + k];
                o[i][0] = fmaf(p, v4.x, o[i][0]);
                o[i][1] = fmaf(p, v4.y, o[i][1]);
                o[i][2] = fmaf(p, v4.z, o[i][2]);
                o[i][3] = fmaf(p, v4.w, o[i][3]);
            }
        }
        __syncthreads();
    }

    // epilogue: normalize, write attended [b*QLEN + q][h*64 + c]
    float* Og = O + ((size_t)(b * QLEN + q0)) * EMBED + h * HDIM;
    #pragma unroll
    for (int i = 0; i < 8; i++) {
        float inv = 1.f / l[i];
        float4 r = make_float4(o[i][0] * inv, o[i][1] * inv,
                               o[i][2] * inv, o[i][3] * inv);
        *(float4*)&Og[(size_t)(tr * 8 + i) * EMBED + tc * 4] = r;
    }
}

// ---------------- launcher --------------------------------------------------
extern "C" void kernel_launch(void* const* d_in, const int* in_sizes, int n_in,
                              void* d_out, int out_size)
{
    (void)in_sizes; (void)n_in; (void)out_size;
    const float* query   = (const float*)d_in[0];
    const float* context = (const float*)d_in[1];
    const float* Wq = (const float*)d_in[2];
    const float* bq = (const float*)d_in[3];
    const float* Wk = (const float*)d_in[4];
    const float* bk = (const float*)d_in[5];
    const float* Wv = (const float*)d_in[6];
    const float* bv = (const float*)d_in[7];
    const float* Wo = (const float*)d_in[8];
    const float* bo = (const float*)d_in[9];

    float *Qb, *Kb, *Vb, *Ab;
    cudaGetSymbolAddress((void**)&Qb, g_Q);
    cudaGetSymbolAddress((void**)&Kb, g_K);
    cudaGetSymbolAddress((void**)&Vb, g_V);
    cudaGetSymbolAddress((void**)&Ab, g_A);

    dim3 gemm_grid(EMBED / 128, ROWS / 128);   // (8, 32)
    sgemm_bias<<<gemm_grid, 256>>>(query,   Wq, bq, Qb);
    sgemm_bias<<<gemm_grid, 256>>>(context, Wk, bk, Kb);
    sgemm_bias<<<gemm_grid, 256>>>(context, Wv, bv, Vb);

    size_t flash_smem = (size_t)FLASH_SMEM_FLOATS * sizeof(float);  // ~165 KB
    cudaFuncSetAttribute(flash_attn, cudaFuncAttributeMaxDynamicSharedMemorySize,
                         (int)flash_smem);
    flash_attn<<<dim3(QLEN / BQ, BATCH * NHEAD), 256, flash_smem>>>(Qb, Kb, Vb, Ab);

    sgemm_bias<<<gemm_grid, 256>>>(Ab, Wo, bo, (float*)d_out);
}